// round 4
// baseline (speedup 1.0000x reference)
#include <cuda_runtime.h>
#include <math_constants.h>

// Problem dims (fixed by the reference)
#define BB 4
#define TT 2048
#define CC 1024
#define HH 16
#define DD 64
#define BT (BB*TT)      // 8192 rows
#define F3 (3*CC)       // 3072 qkv features

// Scratch (allocation-free rule: __device__ globals)
__device__ float g_qkv[BT * F3];   // 100.7 MB
__device__ float g_att[BT * CC];   // 33.6 MB

// ---------------------------------------------------------------------------
// GEMM (NT): C[m][n] = sum_k A[m][k] * W[n][k]
// A: M x K row-major, W: N x K row-major (torch Linear weight layout)
// 128x128 block tile, BK=16, 256 threads, 8x8 per-thread microtile
// ---------------------------------------------------------------------------
__global__ void __launch_bounds__(256, 2) gemm_nt_kernel(
    const float* __restrict__ A, const float* __restrict__ W,
    float* __restrict__ C, int M, int N, int K)
{
    __shared__ float As[16][132];   // [k][m], padded pitch
    __shared__ float Ws[16][132];   // [k][n], padded pitch

    const int tid = threadIdx.x;
    const int tx  = tid & 15;
    const int ty  = tid >> 4;
    const int m0  = blockIdx.y * 128;
    const int n0  = blockIdx.x * 128;

    float acc[8][8];
    #pragma unroll
    for (int i = 0; i < 8; i++)
        #pragma unroll
        for (int j = 0; j < 8; j++) acc[i][j] = 0.f;

    const int lr = tid >> 2;          // base row for cooperative loads (0..63)
    const int lk = (tid & 3) << 2;    // k sub-offset (0,4,8,12)

    for (int k0 = 0; k0 < K; k0 += 16) {
        #pragma unroll
        for (int it = 0; it < 2; it++) {
            int r = lr + it * 64;
            float4 av = *(const float4*)(A + (size_t)(m0 + r) * K + k0 + lk);
            As[lk+0][r] = av.x; As[lk+1][r] = av.y;
            As[lk+2][r] = av.z; As[lk+3][r] = av.w;
            float4 wv = *(const float4*)(W + (size_t)(n0 + r) * K + k0 + lk);
            Ws[lk+0][r] = wv.x; Ws[lk+1][r] = wv.y;
            Ws[lk+2][r] = wv.z; Ws[lk+3][r] = wv.w;
        }
        __syncthreads();

        #pragma unroll
        for (int k = 0; k < 16; k++) {
            float a[8], b[8];
            *(float4*)(a)     = *(const float4*)&As[k][ty*8];
            *(float4*)(a + 4) = *(const float4*)&As[k][ty*8 + 4];
            *(float4*)(b)     = *(const float4*)&Ws[k][tx*8];
            *(float4*)(b + 4) = *(const float4*)&Ws[k][tx*8 + 4];
            #pragma unroll
            for (int i = 0; i < 8; i++)
                #pragma unroll
                for (int j = 0; j < 8; j++)
                    acc[i][j] += a[i] * b[j];
        }
        __syncthreads();
    }

    #pragma unroll
    for (int i = 0; i < 8; i++) {
        float* crow = C + (size_t)(m0 + ty*8 + i) * N + n0 + tx*8;
        *(float4*)(crow)     = make_float4(acc[i][0], acc[i][1], acc[i][2], acc[i][3]);
        *(float4*)(crow + 4) = make_float4(acc[i][4], acc[i][5], acc[i][6], acc[i][7]);
    }
}

// ---------------------------------------------------------------------------
// Flash attention (causal), fp32. One block = one (b,h) x 64 query rows.
// BM=BN=64, D=64. 256 threads as 16x16, 4x4 microtile per thread.
// Online softmax; causal tile-skip: only k-tiles with k0 <= q0 are visited.
// ---------------------------------------------------------------------------
#define AT_BM 64
#define AT_BN 64
#define QP 64
#define KP 65    // natural [key][d] layout, odd pitch -> only 2-way conflicts
#define VP 64
#define PP 68    // float4-aligned padded pitch for P
#define ATT_SMEM ((AT_BM*QP + AT_BN*KP + AT_BN*VP + AT_BM*PP) * 4)  // 66816 B

__global__ void __launch_bounds__(256) attn_kernel(
    const float* __restrict__ qkv, float* __restrict__ att)
{
    extern __shared__ float smem[];
    float* Qs = smem;                  // [64][QP]  (pre-scaled Q)
    float* Ks = Qs + AT_BM * QP;       // [64][KP]  [key][d]
    float* Vs = Ks + AT_BN * KP;       // [64][VP]  [key][d]
    float* Ps = Vs + AT_BN * VP;       // [64][PP]  softmax weights

    const int tid = threadIdx.x;
    const int tx  = tid & 15;
    const int ty  = tid >> 4;
    const int bh  = blockIdx.y;
    const int b   = bh >> 4;       // bh / HH
    const int h   = bh & 15;       // bh % HH
    const int q0  = blockIdx.x * AT_BM;

    const float* qbase = qkv + (size_t)(b*TT + q0) * F3 + h*DD;
    const float* kbase = qkv + (size_t)(b*TT) * F3 + CC   + h*DD;
    const float* vbase = qkv + (size_t)(b*TT) * F3 + 2*CC + h*DD;

    // Load Q tile, folding in 1/sqrt(D) = 0.125
    {
        const float scale = 0.125f;
        #pragma unroll
        for (int it = 0; it < 4; it++) {
            int fi = tid + it * 256;
            int r  = fi >> 4;
            int d0 = (fi & 15) << 2;
            float4 v = *(const float4*)(qbase + (size_t)r * F3 + d0);
            float* q = Qs + r * QP + d0;
            q[0] = v.x * scale; q[1] = v.y * scale;
            q[2] = v.z * scale; q[3] = v.w * scale;
        }
    }

    float m_i[4], l_i[4], acc[4][4];
    #pragma unroll
    for (int i = 0; i < 4; i++) {
        m_i[i] = -CUDART_INF_F;
        l_i[i] = 0.f;
        #pragma unroll
        for (int j = 0; j < 4; j++) acc[i][j] = 0.f;
    }

    const int nkt = (q0 >> 6) + 1;
    for (int kt = 0; kt < nkt; kt++) {
        const int k0 = kt * AT_BN;

        __syncthreads();  // prior readers of Ks/Vs done; also orders Q load on iter 0
        #pragma unroll
        for (int it = 0; it < 4; it++) {
            int fi = tid + it * 256;
            int r  = fi >> 4;
            int d0 = (fi & 15) << 2;
            float4 kv = *(const float4*)(kbase + (size_t)(k0 + r) * F3 + d0);
            float* kd = Ks + r * KP + d0;
            kd[0] = kv.x; kd[1] = kv.y; kd[2] = kv.z; kd[3] = kv.w;
            float4 vv = *(const float4*)(vbase + (size_t)(k0 + r) * F3 + d0);
            *(float4*)(Vs + r * VP + d0) = vv;
        }
        __syncthreads();

        // S = (Q*scale) K^T  (4x4 per thread)
        float s[4][4];
        #pragma unroll
        for (int i = 0; i < 4; i++)
            #pragma unroll
            for (int j = 0; j < 4; j++) s[i][j] = 0.f;

        #pragma unroll 16
        for (int d = 0; d < DD; d++) {
            float a[4], bb[4];
            #pragma unroll
            for (int i = 0; i < 4; i++) a[i]  = Qs[(ty*4 + i) * QP + d];
            #pragma unroll
            for (int j = 0; j < 4; j++) bb[j] = Ks[(tx*4 + j) * KP + d];
            #pragma unroll
            for (int i = 0; i < 4; i++)
                #pragma unroll
                for (int j = 0; j < 4; j++)
                    s[i][j] += a[i] * bb[j];
        }

        // Causal mask only on the diagonal tile (k0 == q0)
        if (k0 == q0) {
            #pragma unroll
            for (int i = 0; i < 4; i++)
                #pragma unroll
                for (int j = 0; j < 4; j++)
                    if (tx*4 + j > ty*4 + i) s[i][j] = -CUDART_INF_F;
        }

        // Online softmax per row; rows of a 16-lane group are reduced via shfl
        float p[4][4];
        #pragma unroll
        for (int i = 0; i < 4; i++) {
            float tm = fmaxf(fmaxf(s[i][0], s[i][1]), fmaxf(s[i][2], s[i][3]));
            #pragma unroll
            for (int off = 1; off < 16; off <<= 1)
                tm = fmaxf(tm, __shfl_xor_sync(0xffffffffu, tm, off));
            float mn = fmaxf(m_i[i], tm);
            float sc = __expf(m_i[i] - mn);   // exp(-inf - finite) = 0 on first tile
            m_i[i] = mn;
            float rs = 0.f;
            #pragma unroll
            for (int j = 0; j < 4; j++) {
                p[i][j] = __expf(s[i][j] - mn);  // masked -> exp(-inf) = 0
                rs += p[i][j];
            }
            #pragma unroll
            for (int off = 1; off < 16; off <<= 1)
                rs += __shfl_xor_sync(0xffffffffu, rs, off);
            l_i[i] = l_i[i] * sc + rs;
            #pragma unroll
            for (int j = 0; j < 4; j++) acc[i][j] *= sc;
        }

        // Stage P; producer/consumer of each row-group are the same half-warp,
        // so __syncwarp suffices (no block barrier needed here).
        #pragma unroll
        for (int i = 0; i < 4; i++)
            *(float4*)(Ps + (ty*4 + i) * PP + tx*4) =
                make_float4(p[i][0], p[i][1], p[i][2], p[i][3]);
        __syncwarp();

        // O += P @ V
        #pragma unroll 16
        for (int k = 0; k < AT_BN; k++) {
            float4 vv = *(const float4*)(Vs + k * VP + tx*4);
            #pragma unroll
            for (int i = 0; i < 4; i++) {
                float pv = Ps[(ty*4 + i) * PP + k];
                acc[i][0] += pv * vv.x;
                acc[i][1] += pv * vv.y;
                acc[i][2] += pv * vv.z;
                acc[i][3] += pv * vv.w;
            }
        }
    }

    // Epilogue: normalize and write [B,T,C] with head-interleaved columns
    #pragma unroll
    for (int i = 0; i < 4; i++) {
        float inv = 1.0f / l_i[i];
        float* orow = att + (size_t)(b*TT + q0 + ty*4 + i) * CC + h*DD + tx*4;
        *(float4*)orow = make_float4(acc[i][0]*inv, acc[i][1]*inv,
                                     acc[i][2]*inv, acc[i][3]*inv);
    }
}

// ---------------------------------------------------------------------------
// Launch: QKV GEMM -> flash attention -> proj GEMM (all graph-capturable)
// ---------------------------------------------------------------------------
extern "C" void kernel_launch(void* const* d_in, const int* in_sizes, int n_in,
                              void* d_out, int out_size)
{
    (void)in_sizes; (void)n_in; (void)out_size;
    const float* x      = (const float*)d_in[0];
    const float* w_qkv  = (const float*)d_in[1];
    const float* w_proj = (const float*)d_in[2];
    float* out = (float*)d_out;

    float* qkv = nullptr;
    float* attb = nullptr;
    cudaGetSymbolAddress((void**)&qkv,  g_qkv);
    cudaGetSymbolAddress((void**)&attb, g_att);

    cudaFuncSetAttribute(attn_kernel,
                         cudaFuncAttributeMaxDynamicSharedMemorySize, ATT_SMEM);

    dim3 g1(F3 / 128, BT / 128);        // (24, 64)
    gemm_nt_kernel<<<g1, 256>>>(x, w_qkv, qkv, BT, F3, CC);

    dim3 g2(TT / AT_BM, BB * HH);       // (32, 64)
    attn_kernel<<<g2, 256, ATT_SMEM>>>(qkv, attb);

    dim3 g3(CC / 128, BT / 128);        // (8, 64)
    gemm_nt_kernel<<<g3, 256>>>(attb, w_proj, out, BT, CC, CC);
}

// round 5
// speedup vs baseline: 1.1104x; 1.1104x over previous
#include <cuda_runtime.h>
#include <math_constants.h>

// Problem dims (fixed by the reference)
#define BB 4
#define TT 2048
#define CC 1024
#define HH 16
#define DD 64
#define BT (BB*TT)      // 8192 rows
#define F3 (3*CC)       // 3072 qkv features

// Scratch (allocation-free rule: __device__ globals)
__device__ float g_qkv[BT * F3];   // 100.7 MB
__device__ float g_att[BT * CC];   // 33.6 MB

// ---------------------------------------------------------------------------
// Tensor-core GEMM (NT): C[m][n] = sum_k A[m][k] * W[n][k]
// mma.sync.m16n8k8 tf32, 3xTF32 split for fp32-level accuracy.
// Block 128x128, BK=16, 256 threads = 8 warps (2 m x 4 n), warp tile 64x32.
// cp.async double-buffered K pipeline.
// ---------------------------------------------------------------------------
#define APITCH 20   // floats per smem row (16 data + 4 pad): conflict-free frags,
                    // 16B-aligned cp.async targets (20*4=80 bytes)

__device__ __forceinline__ void cp16(void* dst, const void* src) {
    unsigned d = (unsigned)__cvta_generic_to_shared(dst);
    asm volatile("cp.async.cg.shared.global [%0], [%1], 16;\n" :: "r"(d), "l"(src));
}
#define CP_COMMIT() asm volatile("cp.async.commit_group;\n" ::: "memory")
#define CP_WAIT(n)  asm volatile("cp.async.wait_group %0;\n" :: "n"(n) : "memory")

__device__ __forceinline__ void split_tf32(float x, unsigned& hi, unsigned& lo) {
    unsigned h; asm("cvt.rna.tf32.f32 %0, %1;" : "=r"(h) : "f"(x));
    float r = x - __uint_as_float(h);
    unsigned l; asm("cvt.rna.tf32.f32 %0, %1;" : "=r"(l) : "f"(r));
    hi = h; lo = l;
}

__device__ __forceinline__ void mma_tf32(float c[4], const unsigned a[4],
                                         unsigned b0, unsigned b1) {
    asm volatile(
        "mma.sync.aligned.m16n8k8.row.col.f32.tf32.tf32.f32 "
        "{%0,%1,%2,%3},{%4,%5,%6,%7},{%8,%9},{%0,%1,%2,%3};"
        : "+f"(c[0]), "+f"(c[1]), "+f"(c[2]), "+f"(c[3])
        : "r"(a[0]), "r"(a[1]), "r"(a[2]), "r"(a[3]), "r"(b0), "r"(b1));
}

__global__ void __launch_bounds__(256) gemm_nt_tc_kernel(
    const float* __restrict__ A, const float* __restrict__ W,
    float* __restrict__ C, int M, int N, int K)
{
    __shared__ float As[2][128 * APITCH];
    __shared__ float Bs[2][128 * APITCH];

    const int tid    = threadIdx.x;
    const int lane   = tid & 31;
    const int warp   = tid >> 5;
    const int warp_m = warp >> 2;          // 0..1  -> 64-row slab
    const int warp_n = warp & 3;           // 0..3  -> 32-col slab
    const int lr     = lane >> 2;          // 0..7
    const int lc     = lane & 3;           // 0..3
    const int m0     = blockIdx.y * 128;
    const int n0     = blockIdx.x * 128;

    float acc[4][4][4];                    // [mt][nt][frag]
    #pragma unroll
    for (int i = 0; i < 4; i++)
        #pragma unroll
        for (int j = 0; j < 4; j++)
            #pragma unroll
            for (int f = 0; f < 4; f++) acc[i][j][f] = 0.f;

    // cooperative tile loader: 128 rows x 16 floats for A and W, 16B chunks
    auto load_tile = [&](int st, int k0) {
        #pragma unroll
        for (int it = 0; it < 2; it++) {
            int c   = tid + it * 256;      // 0..511 chunk id
            int row = c >> 2;
            int kk  = (c & 3) << 2;
            cp16(&As[st][row * APITCH + kk], A + (size_t)(m0 + row) * K + k0 + kk);
            cp16(&Bs[st][row * APITCH + kk], W + (size_t)(n0 + row) * K + k0 + kk);
        }
    };

    const int KT = K >> 4;                 // k-tiles of 16
    load_tile(0, 0);
    CP_COMMIT();

    for (int kt = 0; kt < KT; kt++) {
        if (kt + 1 < KT) {
            load_tile((kt + 1) & 1, (kt + 1) << 4);
            CP_COMMIT();
            CP_WAIT(1);
        } else {
            CP_WAIT(0);
        }
        __syncthreads();

        const int st = kt & 1;
        const float* as = As[st] + (warp_m * 64) * APITCH;
        const float* bs = Bs[st] + (warp_n * 32) * APITCH;

        #pragma unroll
        for (int k8 = 0; k8 < 16; k8 += 8) {
            unsigned ahi[4][4], alo[4][4];
            #pragma unroll
            for (int mt = 0; mt < 4; mt++) {
                const float* p = as + (mt * 16 + lr) * APITCH + k8 + lc;
                float a0 = p[0];
                float a1 = p[8 * APITCH];
                float a2 = p[4];
                float a3 = p[8 * APITCH + 4];
                split_tf32(a0, ahi[mt][0], alo[mt][0]);
                split_tf32(a1, ahi[mt][1], alo[mt][1]);
                split_tf32(a2, ahi[mt][2], alo[mt][2]);
                split_tf32(a3, ahi[mt][3], alo[mt][3]);
            }
            #pragma unroll
            for (int nt = 0; nt < 4; nt++) {
                const float* p = bs + (nt * 8 + lr) * APITCH + k8 + lc;
                float b0 = p[0];
                float b1 = p[4];
                unsigned bh0, bl0, bh1, bl1;
                split_tf32(b0, bh0, bl0);
                split_tf32(b1, bh1, bl1);
                #pragma unroll
                for (int mt = 0; mt < 4; mt++) {
                    mma_tf32(acc[mt][nt], ahi[mt], bh0, bh1);  // hi*hi
                    mma_tf32(acc[mt][nt], ahi[mt], bl0, bl1);  // hi*lo
                    mma_tf32(acc[mt][nt], alo[mt], bh0, bh1);  // lo*hi
                }
            }
        }
        __syncthreads();
    }

    // Epilogue: C fragment -> gmem (float2 per half-row pair)
    #pragma unroll
    for (int mt = 0; mt < 4; mt++) {
        #pragma unroll
        for (int nt = 0; nt < 4; nt++) {
            int r  = m0 + warp_m * 64 + mt * 16 + lr;
            int cc = n0 + warp_n * 32 + nt * 8 + 2 * lc;
            float2* p0 = (float2*)(C + (size_t)r * N + cc);
            float2* p1 = (float2*)(C + (size_t)(r + 8) * N + cc);
            *p0 = make_float2(acc[mt][nt][0], acc[mt][nt][1]);
            *p1 = make_float2(acc[mt][nt][2], acc[mt][nt][3]);
        }
    }
}

// ---------------------------------------------------------------------------
// Flash attention (causal), fp32. One block = one (b,h) x 64 query rows.
// BM=BN=64, D=64. 256 threads as 16x16, 4x4 microtile per thread.
// Online softmax; causal tile-skip: only k-tiles with k0 <= q0 are visited.
// ---------------------------------------------------------------------------
#define AT_BM 64
#define AT_BN 64
#define QP 64
#define KP 65    // natural [key][d] layout, odd pitch -> only 2-way conflicts
#define VP 64
#define PP 68    // float4-aligned padded pitch for P
#define ATT_SMEM ((AT_BM*QP + AT_BN*KP + AT_BN*VP + AT_BM*PP) * 4)  // 66816 B

__global__ void __launch_bounds__(256) attn_kernel(
    const float* __restrict__ qkv, float* __restrict__ att)
{
    extern __shared__ float smem[];
    float* Qs = smem;                  // [64][QP]  (pre-scaled Q)
    float* Ks = Qs + AT_BM * QP;       // [64][KP]  [key][d]
    float* Vs = Ks + AT_BN * KP;       // [64][VP]  [key][d]
    float* Ps = Vs + AT_BN * VP;       // [64][PP]  softmax weights

    const int tid = threadIdx.x;
    const int tx  = tid & 15;
    const int ty  = tid >> 4;
    const int bh  = blockIdx.y;
    const int b   = bh >> 4;       // bh / HH
    const int h   = bh & 15;       // bh % HH
    const int q0  = blockIdx.x * AT_BM;

    const float* qbase = qkv + (size_t)(b*TT + q0) * F3 + h*DD;
    const float* kbase = qkv + (size_t)(b*TT) * F3 + CC   + h*DD;
    const float* vbase = qkv + (size_t)(b*TT) * F3 + 2*CC + h*DD;

    // Load Q tile, folding in 1/sqrt(D) = 0.125
    {
        const float scale = 0.125f;
        #pragma unroll
        for (int it = 0; it < 4; it++) {
            int fi = tid + it * 256;
            int r  = fi >> 4;
            int d0 = (fi & 15) << 2;
            float4 v = *(const float4*)(qbase + (size_t)r * F3 + d0);
            float* q = Qs + r * QP + d0;
            q[0] = v.x * scale; q[1] = v.y * scale;
            q[2] = v.z * scale; q[3] = v.w * scale;
        }
    }

    float m_i[4], l_i[4], acc[4][4];
    #pragma unroll
    for (int i = 0; i < 4; i++) {
        m_i[i] = -CUDART_INF_F;
        l_i[i] = 0.f;
        #pragma unroll
        for (int j = 0; j < 4; j++) acc[i][j] = 0.f;
    }

    const int nkt = (q0 >> 6) + 1;
    for (int kt = 0; kt < nkt; kt++) {
        const int k0 = kt * AT_BN;

        __syncthreads();  // prior readers of Ks/Vs done; also orders Q load on iter 0
        #pragma unroll
        for (int it = 0; it < 4; it++) {
            int fi = tid + it * 256;
            int r  = fi >> 4;
            int d0 = (fi & 15) << 2;
            float4 kv = *(const float4*)(kbase + (size_t)(k0 + r) * F3 + d0);
            float* kd = Ks + r * KP + d0;
            kd[0] = kv.x; kd[1] = kv.y; kd[2] = kv.z; kd[3] = kv.w;
            float4 vv = *(const float4*)(vbase + (size_t)(k0 + r) * F3 + d0);
            *(float4*)(Vs + r * VP + d0) = vv;
        }
        __syncthreads();

        // S = (Q*scale) K^T  (4x4 per thread)
        float s[4][4];
        #pragma unroll
        for (int i = 0; i < 4; i++)
            #pragma unroll
            for (int j = 0; j < 4; j++) s[i][j] = 0.f;

        #pragma unroll 16
        for (int d = 0; d < DD; d++) {
            float a[4], bb[4];
            #pragma unroll
            for (int i = 0; i < 4; i++) a[i]  = Qs[(ty*4 + i) * QP + d];
            #pragma unroll
            for (int j = 0; j < 4; j++) bb[j] = Ks[(tx*4 + j) * KP + d];
            #pragma unroll
            for (int i = 0; i < 4; i++)
                #pragma unroll
                for (int j = 0; j < 4; j++)
                    s[i][j] += a[i] * bb[j];
        }

        // Causal mask only on the diagonal tile (k0 == q0)
        if (k0 == q0) {
            #pragma unroll
            for (int i = 0; i < 4; i++)
                #pragma unroll
                for (int j = 0; j < 4; j++)
                    if (tx*4 + j > ty*4 + i) s[i][j] = -CUDART_INF_F;
        }

        // Online softmax per row; rows of a 16-lane group are reduced via shfl
        float p[4][4];
        #pragma unroll
        for (int i = 0; i < 4; i++) {
            float tm = fmaxf(fmaxf(s[i][0], s[i][1]), fmaxf(s[i][2], s[i][3]));
            #pragma unroll
            for (int off = 1; off < 16; off <<= 1)
                tm = fmaxf(tm, __shfl_xor_sync(0xffffffffu, tm, off));
            float mn = fmaxf(m_i[i], tm);
            float sc = __expf(m_i[i] - mn);   // exp(-inf - finite) = 0 on first tile
            m_i[i] = mn;
            float rs = 0.f;
            #pragma unroll
            for (int j = 0; j < 4; j++) {
                p[i][j] = __expf(s[i][j] - mn);  // masked -> exp(-inf) = 0
                rs += p[i][j];
            }
            #pragma unroll
            for (int off = 1; off < 16; off <<= 1)
                rs += __shfl_xor_sync(0xffffffffu, rs, off);
            l_i[i] = l_i[i] * sc + rs;
            #pragma unroll
            for (int j = 0; j < 4; j++) acc[i][j] *= sc;
        }

        // Stage P; producer/consumer of each row-group are the same half-warp,
        // so __syncwarp suffices (no block barrier needed here).
        #pragma unroll
        for (int i = 0; i < 4; i++)
            *(float4*)(Ps + (ty*4 + i) * PP + tx*4) =
                make_float4(p[i][0], p[i][1], p[i][2], p[i][3]);
        __syncwarp();

        // O += P @ V
        #pragma unroll 16
        for (int k = 0; k < AT_BN; k++) {
            float4 vv = *(const float4*)(Vs + k * VP + tx*4);
            #pragma unroll
            for (int i = 0; i < 4; i++) {
                float pv = Ps[(ty*4 + i) * PP + k];
                acc[i][0] += pv * vv.x;
                acc[i][1] += pv * vv.y;
                acc[i][2] += pv * vv.z;
                acc[i][3] += pv * vv.w;
            }
        }
    }

    // Epilogue: normalize and write [B,T,C] with head-interleaved columns
    #pragma unroll
    for (int i = 0; i < 4; i++) {
        float inv = 1.0f / l_i[i];
        float* orow = att + (size_t)(b*TT + q0 + ty*4 + i) * CC + h*DD + tx*4;
        *(float4*)orow = make_float4(acc[i][0]*inv, acc[i][1]*inv,
                                     acc[i][2]*inv, acc[i][3]*inv);
    }
}

// ---------------------------------------------------------------------------
// Launch: QKV GEMM (TC) -> flash attention -> proj GEMM (TC)
// ---------------------------------------------------------------------------
extern "C" void kernel_launch(void* const* d_in, const int* in_sizes, int n_in,
                              void* d_out, int out_size)
{
    (void)in_sizes; (void)n_in; (void)out_size;
    const float* x      = (const float*)d_in[0];
    const float* w_qkv  = (const float*)d_in[1];
    const float* w_proj = (const float*)d_in[2];
    float* out = (float*)d_out;

    float* qkv = nullptr;
    float* attb = nullptr;
    cudaGetSymbolAddress((void**)&qkv,  g_qkv);
    cudaGetSymbolAddress((void**)&attb, g_att);

    cudaFuncSetAttribute(attn_kernel,
                         cudaFuncAttributeMaxDynamicSharedMemorySize, ATT_SMEM);

    dim3 g1(F3 / 128, BT / 128);        // (24, 64)
    gemm_nt_tc_kernel<<<g1, 256>>>(x, w_qkv, qkv, BT, F3, CC);

    dim3 g2(TT / AT_BM, BB * HH);       // (32, 64)
    attn_kernel<<<g2, 256, ATT_SMEM>>>(qkv, attb);

    dim3 g3(CC / 128, BT / 128);        // (8, 64)
    gemm_nt_tc_kernel<<<g3, 256>>>(attb, w_proj, out, BT, CC, CC);
}